// round 12
// baseline (speedup 1.0000x reference)
#include <cuda_runtime.h>
#include <stdint.h>

#define B 64
#define H 1024
#define S 4096
#define NOPS 8
#define TSTEPS 10

typedef unsigned long long ull;

// ---- ka: 64 combine + 1 ctrl + 16 op + 256 GEMM (tile 64b x 128s, split 8) --
#define K1_SB 128
#define K1_NSB (S / K1_SB)           // 32
#define K1_KSPLIT 8
#define K1_KR (H / K1_KSPLIT)        // 128
#define K1_KC 16
#define K1_NC (K1_KR / K1_KC)        // 8
#define K1_GEMM (K1_NSB * K1_KSPLIT) // 256
#define KA_NCOMB 64
#define KA_CTRL  64
#define KA_OP0   65
#define KA_NOPB  16
#define KA_GEMM0 (KA_OP0 + KA_NOPB)  // 81
#define KA_GRID  (KA_GEMM0 + K1_GEMM) // 337

// ---- kb: 256 argmax + 256 GEMM (tile 64b x 64j, split 16, gather-first) ----
#define K2_JB 64
#define K2_NJB (H / K2_JB)           // 16
#define K2_KSPLIT 16
#define K2_K (2 * H)
#define K2_KR (K2_K / K2_KSPLIT)     // 128
#define K2_KC 16
#define K2_NC (K2_KR / K2_KC)        // 8
#define K2_GEMM (K2_NJB * K2_KSPLIT) // 256
#define NAMB 256
#define KB_GRID (NAMB + K2_GEMM)     // 512

// ---- persistent scratch ----
__device__ float g_hn[B * H];
__device__ float g_px[K1_KSPLIT][B][S];   // 8 MB
__device__ float g_pu[K2_KSPLIT][B][H];   // 4 MB
__device__ ull   g_amax[B];
__device__ int   g_opflag[TSTEPS][B];
__device__ int   g_done_flag[TSTEPS];
__device__ int   g_arrived;
__device__ int   g_cnt_hn[TSTEPS];

__device__ __forceinline__ ull ffma2(ull a, ull b, ull c) {
    ull d;
    asm("fma.rn.f32x2 %0, %1, %2, %3;" : "=l"(d) : "l"(a), "l"(b), "l"(c));
    return d;
}
__device__ __forceinline__ unsigned f2ord(float f) {
    unsigned u = __float_as_uint(f);
    return (u & 0x80000000u) ? ~u : (u | 0x80000000u);
}
__device__ __forceinline__ float2 dupf(float x) { return make_float2(x, x); }

__device__ __forceinline__ void spin_until(int* cnt, int target) {
    if (threadIdx.x == 0) {
        while (*(volatile int*)cnt < target) __nanosleep(128);
    }
    __syncthreads();
    __threadfence();
}

// ============ KA: combine + ctrl + op-logits + x-logit GEMM =================
__global__ __launch_bounds__(256) void ka(
    int t, const float* __restrict__ Wx,
    const float* __restrict__ Wop, const float* __restrict__ bop,
    const float* __restrict__ bres, const float* __restrict__ noise)
{
    __shared__ __align__(16) char smem[2 * K1_KC * 64 * 8 + 2 * K1_KC * K1_SB * 4];
    const int tid = threadIdx.x;
    const int bid = blockIdx.x;

    if (bid < KA_NCOMB) {
        // ------- combine block: one batch row, 256 j-quads, MLP-16 -------
        const int b = bid;
        const int j = tid * 4;
        float4 a = make_float4(0.f, 0.f, 0.f, 0.f);
        if (t > 0) {
#pragma unroll
            for (int ks = 0; ks < K2_KSPLIT; ks++) {
                float4 p = *(const float4*)&g_pu[ks][b][j];
                a.x += p.x; a.y += p.y; a.z += p.z; a.w += p.w;
            }
            float4 bb = *(const float4*)&bres[j];
            a.x += bb.x; a.y += bb.y; a.z += bb.z; a.w += bb.w;
        }
        float4 nz = *(const float4*)&noise[((size_t)t * B + b) * H + j];
        *(float4*)&g_hn[b * H + j] =
            make_float4(a.x + 0.01f * nz.x, a.y + 0.01f * nz.y,
                        a.z + 0.01f * nz.z, a.w + 0.01f * nz.w);
        __threadfence();
        __syncthreads();
        if (tid == 0) atomicAdd(&g_cnt_hn[t], 1);
        return;
    }

    if (bid == KA_CTRL) {
        // ------- ctrl: done flag + per-step resets (before kb launches) ---
        int dn = 0;
        for (int tp = 0; tp < t; tp++) {
            int f = (tid < B) ? g_opflag[tp][tid] : 1;
            dn |= __syncthreads_and(f);
        }
        if (tid == 0) { g_done_flag[t] = dn; g_arrived = 0; }
        if (tid < B) g_amax[tid] = 0ull;
        return;
    }

    if (bid < KA_GEMM0) {
        // ------- op-logits block: 4 batch rows, full K -------
        float (*sOp)[64][NOPS] = (float(*)[64][NOPS])smem;               // 8 KB
        float (*sSum)[NOPS] = (float(*)[NOPS])(smem + 4 * 64 * NOPS * 4 + 128);
        spin_until(&g_cnt_hn[t], KA_NCOMB);
        const float* __restrict__ hn = g_hn;
        const int b0 = (bid - KA_OP0) * 4;
        const int lb = tid >> 6, seg = tid & 63;
        const int b = b0 + lb, kb = seg * 16;
        float part[NOPS];
#pragma unroll
        for (int o = 0; o < NOPS; o++) part[o] = 0.f;
        const float4* wp = (const float4*)(Wop + (size_t)kb * NOPS);
#pragma unroll
        for (int g = 0; g < 4; g++) {
            float4 a4 = *(const float4*)&hn[b * H + kb + g * 4];
            float av[4] = {a4.x, a4.y, a4.z, a4.w};
#pragma unroll
            for (int c = 0; c < 4; c++) {
                float4 w0 = wp[(g * 4 + c) * 2], w1 = wp[(g * 4 + c) * 2 + 1];
                float aa = av[c];
                part[0] += aa * w0.x; part[1] += aa * w0.y;
                part[2] += aa * w0.z; part[3] += aa * w0.w;
                part[4] += aa * w1.x; part[5] += aa * w1.y;
                part[6] += aa * w1.z; part[7] += aa * w1.w;
            }
        }
#pragma unroll
        for (int o = 0; o < NOPS; o++) sOp[lb][seg][o] = part[o];
        __syncthreads();
        if (tid < 32) {
            int rb = tid >> 3, o = tid & 7;
            float s = 0.f;
            for (int g = 0; g < 64; g++) s += sOp[rb][g][o];
            sSum[rb][o] = s;
        }
        __syncthreads();
        if (tid < 4) {
            float best = __int_as_float(0xff800000); int bi = -1;
#pragma unroll
            for (int o = 0; o < NOPS; o++) {
                float v = sSum[tid][o] + bop[o];
                if (v > best) { best = v; bi = o; }
            }
            g_opflag[t][b0 + tid] = (bi == 0) ? 1 : 0;
        }
        return;
    }

    // ------- GEMM block: A dup (16KB) + B raw (16KB), K-depth 128 -------
    float2 (*sA)[K1_KC][64] = (float2(*)[K1_KC][64])smem;
    float  (*sB)[K1_KC][K1_SB] = (float(*)[K1_KC][K1_SB])(smem + 2 * K1_KC * 64 * 8);

    const int g = bid - KA_GEMM0;
    const int ks = g >> 5, sb = g & 31;
    const int s0 = sb * K1_SB, k0 = ks * K1_KR;
    const int sx = tid & 15, byy = tid >> 4;
    const int fb = tid >> 2, fg = tid & 3;     // A fill
    const int wk = tid >> 4, wg = tid & 15;    // B fill

    ull acc[4][4];
#pragma unroll
    for (int p = 0; p < 4; p++)
#pragma unroll
        for (int q = 0; q < 4; q++) acc[p][q] = 0ull;

    {   // B chunk-0 prefetch (independent of h_n) — hides the combine spin
        const float* wr = Wx + (size_t)(k0 + wk) * S + s0 + wg * 8;
        *(float4*)&sB[0][wk][wg * 8]     = *(const float4*)wr;
        *(float4*)&sB[0][wk][wg * 8 + 4] = *(const float4*)(wr + 4);
    }

    spin_until(&g_cnt_hn[t], KA_NCOMB);
    const float* __restrict__ hn = g_hn;

    {   // A chunk 0
        float4 a = *(const float4*)&hn[fb * H + k0 + fg * 4];
        sA[0][fg * 4 + 0][fb] = dupf(a.x);
        sA[0][fg * 4 + 1][fb] = dupf(a.y);
        sA[0][fg * 4 + 2][fb] = dupf(a.z);
        sA[0][fg * 4 + 3][fb] = dupf(a.w);
    }
    __syncthreads();

    for (int c = 0; c < K1_NC; c++) {
        const int cur = c & 1;
        float4 pa, pw0, pw1;
        if (c + 1 < K1_NC) {
            const int kb = k0 + (c + 1) * K1_KC;
            pa = *(const float4*)&hn[fb * H + kb + fg * 4];
            const float* wr = Wx + (size_t)(kb + wk) * S + s0 + wg * 8;
            pw0 = *(const float4*)wr;
            pw1 = *(const float4*)(wr + 4);
        }
#pragma unroll
        for (int kk = 0; kk < K1_KC; kk++) {
            ulonglong2 a01 = *(const ulonglong2*)&sA[cur][kk][byy * 4];
            ulonglong2 a23 = *(const ulonglong2*)&sA[cur][kk][byy * 4 + 2];
            ulonglong2 w01 = *(const ulonglong2*)&sB[cur][kk][sx * 4];
            ulonglong2 w23 = *(const ulonglong2*)&sB[cur][kk][64 + sx * 4];
            ull av[4] = {a01.x, a01.y, a23.x, a23.y};
#pragma unroll
            for (int p = 0; p < 4; p++) {
                acc[p][0] = ffma2(av[p], w01.x, acc[p][0]);
                acc[p][1] = ffma2(av[p], w01.y, acc[p][1]);
                acc[p][2] = ffma2(av[p], w23.x, acc[p][2]);
                acc[p][3] = ffma2(av[p], w23.y, acc[p][3]);
            }
        }
        if (c + 1 < K1_NC) {
            const int nxt = (c + 1) & 1;
            sA[nxt][fg * 4 + 0][fb] = dupf(pa.x);
            sA[nxt][fg * 4 + 1][fb] = dupf(pa.y);
            sA[nxt][fg * 4 + 2][fb] = dupf(pa.z);
            sA[nxt][fg * 4 + 3][fb] = dupf(pa.w);
            *(float4*)&sB[nxt][wk][wg * 8]     = pw0;
            *(float4*)&sB[nxt][wk][wg * 8 + 4] = pw1;
            __syncthreads();
        }
    }

#pragma unroll
    for (int p = 0; p < 4; p++) {
        const int b = byy * 4 + p;
        *(ulonglong2*)&g_px[ks][b][s0 + sx * 4]      = make_ulonglong2(acc[p][0], acc[p][1]);
        *(ulonglong2*)&g_px[ks][b][s0 + 64 + sx * 4] = make_ulonglong2(acc[p][2], acc[p][3]);
    }
}

// ============ KB: argmax (ids 0-255) + gather-GEMM first + hn-GEMM ==========
__global__ __launch_bounds__(128) void kb(
    int t, const float* __restrict__ s2a, const float* __restrict__ Wres,
    const float* __restrict__ bx)
{
    const int tid = threadIdx.x;

    if (blockIdx.x < NAMB) {
        // ------- argmax partial block: (b, 1024-wide s segment) -------
        __shared__ ull red[4];
        const int b = blockIdx.x >> 2;
        const int sseg = (blockIdx.x & 3) * 1024;
        float best = __int_as_float(0xff800000);
        int bi = 0;
#pragma unroll
        for (int it = 0; it < 2; it++) {
            const int s = sseg + (it * 128 + tid) * 4;
            float4 v = *(const float4*)&bx[s];
#pragma unroll
            for (int ks = 0; ks < K1_KSPLIT; ks++) {
                float4 p = *(const float4*)&g_px[ks][b][s];
                v.x += p.x; v.y += p.y; v.z += p.z; v.w += p.w;
            }
            if (v.x > best) { best = v.x; bi = s; }
            if (v.y > best) { best = v.y; bi = s + 1; }
            if (v.z > best) { best = v.z; bi = s + 2; }
            if (v.w > best) { best = v.w; bi = s + 3; }
        }
        ull key = ((ull)f2ord(best) << 32) | (ull)(0xFFFFFFFFu - (unsigned)bi);
#pragma unroll
        for (int off = 16; off; off >>= 1) {
            ull o = __shfl_down_sync(0xFFFFFFFFu, key, off);
            if (o > key) key = o;
        }
        if ((tid & 31) == 0) red[tid >> 5] = key;
        __syncthreads();
        if (tid == 0) {
            ull k = red[0];
#pragma unroll
            for (int w = 1; w < 4; w++) if (red[w] > k) k = red[w];
            atomicMax(&g_amax[b], k);
            __threadfence();
            atomicAdd(&g_arrived, 1);
        }
        return;
    }

    // ------- update GEMM block: 64b x 64j; gather ks (8-15) scheduled FIRST --
    if (g_done_flag[t]) return;   // frozen: keep pu (h stays fixed)

    __shared__ __align__(16) float2 sA[2][K2_KC][B];       // 16 KB (dup)
    __shared__ __align__(16) float  sB[2][K2_KC][K2_JB];   // 8 KB (raw)
    __shared__ int sPtr[B];

    const int q = blockIdx.x - NAMB;
    const int ko_ = q >> 4;                       // 0..15 in schedule order
    const int ks = (ko_ < 8) ? (ko_ + 8) : (ko_ - 8);  // gather ks first
    const int jb = q & 15;
    const int k0 = ks * K2_KR, j0 = jb * K2_JB;
    const bool gat = (k0 >= H);
    const float* __restrict__ hn = g_hn;
    const int jx = tid & 7, byy = tid >> 3;
    const int fbA = tid >> 1, fgA = tid & 1;   // A fill: 2 float4/thread
    const int wkB = tid >> 3, wgB = tid & 7;   // B fill: 2 float4/thread

    // prefetch B chunk 0 (Wres: independent of ptr)
    {
        const float* wr = Wres + (size_t)(k0 + wkB) * H + j0 + wgB * 8;
        *(float4*)&sB[0][wkB][wgB * 8]     = *(const float4*)wr;
        *(float4*)&sB[0][wkB][wgB * 8 + 4] = *(const float4*)(wr + 4);
    }

    if (gat) {
        spin_until(&g_arrived, NAMB);
        if (tid < B) {
            ull k = g_amax[tid];
            int p = (int)(0xFFFFFFFFu - (unsigned)(k & 0xFFFFFFFFull));
            sPtr[tid] = (p < S) ? p : (S - 1);
        }
        __syncthreads();
    }

    const float* arow = gat ? s2a + ((size_t)fbA * S + sPtr[fbA]) * H + (k0 - H)
                            : hn + fbA * H + k0;

    {   // A chunk 0
        float4 a0 = *(const float4*)(arow + fgA * 8);
        float4 a1 = *(const float4*)(arow + fgA * 8 + 4);
        sA[0][fgA * 8 + 0][fbA] = dupf(a0.x);
        sA[0][fgA * 8 + 1][fbA] = dupf(a0.y);
        sA[0][fgA * 8 + 2][fbA] = dupf(a0.z);
        sA[0][fgA * 8 + 3][fbA] = dupf(a0.w);
        sA[0][fgA * 8 + 4][fbA] = dupf(a1.x);
        sA[0][fgA * 8 + 5][fbA] = dupf(a1.y);
        sA[0][fgA * 8 + 6][fbA] = dupf(a1.z);
        sA[0][fgA * 8 + 7][fbA] = dupf(a1.w);
    }
    __syncthreads();

    ull acc[4][4];
#pragma unroll
    for (int p = 0; p < 4; p++)
#pragma unroll
        for (int q2 = 0; q2 < 4; q2++) acc[p][q2] = 0ull;

    for (int c = 0; c < K2_NC; c++) {
        const int cur = c & 1;
        float4 pa0, pa1, pw0, pw1;
        if (c + 1 < K2_NC) {
            const int kof = (c + 1) * K2_KC;
            pa0 = *(const float4*)(arow + kof + fgA * 8);
            pa1 = *(const float4*)(arow + kof + fgA * 8 + 4);
            const float* wr = Wres + (size_t)(k0 + kof + wkB) * H + j0 + wgB * 8;
            pw0 = *(const float4*)wr;
            pw1 = *(const float4*)(wr + 4);
        }
#pragma unroll
        for (int kk = 0; kk < K2_KC; kk++) {
            ulonglong2 a01 = *(const ulonglong2*)&sA[cur][kk][byy * 4];
            ulonglong2 a23 = *(const ulonglong2*)&sA[cur][kk][byy * 4 + 2];
            ulonglong2 w01 = *(const ulonglong2*)&sB[cur][kk][jx * 4];
            ulonglong2 w23 = *(const ulonglong2*)&sB[cur][kk][32 + jx * 4];
            ull av[4] = {a01.x, a01.y, a23.x, a23.y};
#pragma unroll
            for (int p = 0; p < 4; p++) {
                acc[p][0] = ffma2(av[p], w01.x, acc[p][0]);
                acc[p][1] = ffma2(av[p], w01.y, acc[p][1]);
                acc[p][2] = ffma2(av[p], w23.x, acc[p][2]);
                acc[p][3] = ffma2(av[p], w23.y, acc[p][3]);
            }
        }
        if (c + 1 < K2_NC) {
            const int nxt = (c + 1) & 1;
            sA[nxt][fgA * 8 + 0][fbA] = dupf(pa0.x);
            sA[nxt][fgA * 8 + 1][fbA] = dupf(pa0.y);
            sA[nxt][fgA * 8 + 2][fbA] = dupf(pa0.z);
            sA[nxt][fgA * 8 + 3][fbA] = dupf(pa0.w);
            sA[nxt][fgA * 8 + 4][fbA] = dupf(pa1.x);
            sA[nxt][fgA * 8 + 5][fbA] = dupf(pa1.y);
            sA[nxt][fgA * 8 + 6][fbA] = dupf(pa1.z);
            sA[nxt][fgA * 8 + 7][fbA] = dupf(pa1.w);
            *(float4*)&sB[nxt][wkB][wgB * 8]     = pw0;
            *(float4*)&sB[nxt][wkB][wgB * 8 + 4] = pw1;
            __syncthreads();
        }
    }

#pragma unroll
    for (int p = 0; p < 4; p++) {
        const int b = byy * 4 + p;
        *(ulonglong2*)&g_pu[ks][b][j0 + jx * 4]      = make_ulonglong2(acc[p][0], acc[p][1]);
        *(ulonglong2*)&g_pu[ks][b][j0 + 32 + jx * 4] = make_ulonglong2(acc[p][2], acc[p][3]);
    }
}

// ===================== KO: final combine -> out + counter resets ============
__global__ __launch_bounds__(256) void ko(const float* __restrict__ bres,
                                          float* __restrict__ out)
{
    const int b = blockIdx.x, tid = threadIdx.x;
    const int j = tid * 4;
    float4 a = make_float4(0.f, 0.f, 0.f, 0.f);
#pragma unroll
    for (int ks = 0; ks < K2_KSPLIT; ks++) {
        float4 p = *(const float4*)&g_pu[ks][b][j];
        a.x += p.x; a.y += p.y; a.z += p.z; a.w += p.w;
    }
    float4 bb = *(const float4*)&bres[j];
    *(float4*)&out[b * H + j] = make_float4(a.x + bb.x, a.y + bb.y,
                                            a.z + bb.z, a.w + bb.w);
    if (blockIdx.x == 0 && tid < TSTEPS) g_cnt_hn[tid] = 0;
}

extern "C" void kernel_launch(void* const* d_in, const int* in_sizes, int n_in,
                              void* d_out, int out_size) {
    const float* s2a   = (const float*)d_in[0];
    const float* Wres  = (const float*)d_in[1];
    const float* bres  = (const float*)d_in[2];
    const float* Wop   = (const float*)d_in[3];
    const float* bop   = (const float*)d_in[4];
    const float* Wx    = (const float*)d_in[5];
    const float* bx    = (const float*)d_in[6];
    const float* noise = (const float*)d_in[7];
    float* out = (float*)d_out;

    for (int t = 0; t < TSTEPS; t++) {
        ka<<<KA_GRID, 256>>>(t, Wx, Wop, bop, bres, noise);
        kb<<<KB_GRID, 128>>>(t, s2a, Wres, bx);
    }
    ko<<<B, 256>>>(bres, out);
}

// round 13
// speedup vs baseline: 1.4046x; 1.4046x over previous
#include <cuda_runtime.h>
#include <stdint.h>

#define B 64
#define H 1024
#define S 4096
#define NOPS 8
#define TSTEPS 10

typedef unsigned long long ull;

// ---- ka: 64 combine + 1 ctrl + 16 op + 512 GEMM (tile 64b x 128s, split 16) --
#define K1_SB 128
#define K1_NSB (S / K1_SB)           // 32
#define K1_KSPLIT 16
#define K1_KR (H / K1_KSPLIT)        // 64
#define K1_KC 16
#define K1_NC (K1_KR / K1_KC)        // 4
#define K1_GEMM (K1_NSB * K1_KSPLIT) // 512
#define KA_NCOMB 64
#define KA_CTRL  64
#define KA_OP0   65
#define KA_NOPB  16
#define KA_GEMM0 (KA_OP0 + KA_NOPB)  // 81
#define KA_GRID  (KA_GEMM0 + K1_GEMM) // 593

// ka smem: sA raw 2*16*64*4 = 8 KB, sB raw 2*16*128*4 = 16 KB
#define KA_SMEM (2 * K1_KC * 64 * 4 + 2 * K1_KC * K1_SB * 4)

// ---- kb (update): tile 64b x 64j, K-split 16, 128-thr blocks ----
#define K2_JB 64
#define K2_NJB (H / K2_JB)           // 16
#define K2_KSPLIT 16
#define K2_K (2 * H)
#define K2_KR (K2_K / K2_KSPLIT)     // 128
#define K2_KC 16
#define K2_NC (K2_KR / K2_KC)        // 8
#define K2_GEMM (K2_NJB * K2_KSPLIT) // 256
#define NAMB 512
#define KB_GRID (NAMB + K2_GEMM)     // 768

// ---- persistent scratch ----
__device__ float g_hn[B * H];
__device__ float g_px[K1_KSPLIT][B][S];   // 16 MB
__device__ float g_pu[K2_KSPLIT][B][H];   // 4 MB
__device__ ull   g_amax[B];
__device__ int   g_opflag[TSTEPS][B];
__device__ int   g_done_flag[TSTEPS];
__device__ int   g_arrived;
__device__ int   g_cnt_hn[TSTEPS];

__device__ __forceinline__ ull ffma2(ull a, ull b, ull c) {
    ull d;
    asm("fma.rn.f32x2 %0, %1, %2, %3;" : "=l"(d) : "l"(a), "l"(b), "l"(c));
    return d;
}
__device__ __forceinline__ ull pk2(float x) {   // (x,x) packed
    ull r;
    asm("mov.b64 %0, {%1, %2};" : "=l"(r) : "f"(x), "f"(x));
    return r;
}
__device__ __forceinline__ unsigned f2ord(float f) {
    unsigned u = __float_as_uint(f);
    return (u & 0x80000000u) ? ~u : (u | 0x80000000u);
}
__device__ __forceinline__ float2 dupf(float x) { return make_float2(x, x); }

// contention-free spin: volatile LOAD (no LTS RMW serialization); fence = acquire
__device__ __forceinline__ void spin_until(int* cnt, int target) {
    if (threadIdx.x == 0) {
        while (*(volatile int*)cnt < target) __nanosleep(64);
    }
    __syncthreads();
    __threadfence();
}

// ============ KA: combine + ctrl + op-logits + x-logit GEMM =================
__global__ __launch_bounds__(256) void ka(
    int t, const float* __restrict__ Wx,
    const float* __restrict__ Wop, const float* __restrict__ bop,
    const float* __restrict__ bres, const float* __restrict__ noise)
{
    __shared__ __align__(16) char smem[KA_SMEM];
    const int tid = threadIdx.x;
    const int bid = blockIdx.x;

    if (bid < KA_NCOMB) {
        // ------- combine block: one batch row, 256 j-quads, MLP-16 -------
        const int b = bid;
        const int j = tid * 4;
        float4 a = make_float4(0.f, 0.f, 0.f, 0.f);
        if (t > 0) {
#pragma unroll
            for (int ks = 0; ks < K2_KSPLIT; ks++) {
                float4 p = *(const float4*)&g_pu[ks][b][j];
                a.x += p.x; a.y += p.y; a.z += p.z; a.w += p.w;
            }
            float4 bb = *(const float4*)&bres[j];
            a.x += bb.x; a.y += bb.y; a.z += bb.z; a.w += bb.w;
        }
        float4 nz = *(const float4*)&noise[((size_t)t * B + b) * H + j];
        *(float4*)&g_hn[b * H + j] =
            make_float4(a.x + 0.01f * nz.x, a.y + 0.01f * nz.y,
                        a.z + 0.01f * nz.z, a.w + 0.01f * nz.w);
        __threadfence();
        __syncthreads();
        if (tid == 0) atomicAdd(&g_cnt_hn[t], 1);
        return;
    }

    if (bid == KA_CTRL) {
        // ------- ctrl: done flag + per-step resets (before kb launches) ---
        int dn = 0;
        for (int tp = 0; tp < t; tp++) {
            int f = (tid < B) ? g_opflag[tp][tid] : 1;
            dn |= __syncthreads_and(f);
        }
        if (tid == 0) { g_done_flag[t] = dn; g_arrived = 0; }
        if (tid < B) g_amax[tid] = 0ull;
        return;
    }

    if (bid < KA_GEMM0) {
        // ------- op-logits block: 4 batch rows, full K -------
        float (*sOp)[64][NOPS] = (float(*)[64][NOPS])smem;               // 8 KB
        float (*sSum)[NOPS] = (float(*)[NOPS])(smem + 4 * 64 * NOPS * 4 + 128);
        spin_until(&g_cnt_hn[t], KA_NCOMB);
        const float* __restrict__ hn = g_hn;
        const int b0 = (bid - KA_OP0) * 4;
        const int lb = tid >> 6, seg = tid & 63;
        const int b = b0 + lb, kb = seg * 16;
        float part[NOPS];
#pragma unroll
        for (int o = 0; o < NOPS; o++) part[o] = 0.f;
        const float4* wp = (const float4*)(Wop + (size_t)kb * NOPS);
#pragma unroll
        for (int g = 0; g < 4; g++) {
            float4 a4 = *(const float4*)&hn[b * H + kb + g * 4];
            float av[4] = {a4.x, a4.y, a4.z, a4.w};
#pragma unroll
            for (int c = 0; c < 4; c++) {
                float4 w0 = wp[(g * 4 + c) * 2], w1 = wp[(g * 4 + c) * 2 + 1];
                float aa = av[c];
                part[0] += aa * w0.x; part[1] += aa * w0.y;
                part[2] += aa * w0.z; part[3] += aa * w0.w;
                part[4] += aa * w1.x; part[5] += aa * w1.y;
                part[6] += aa * w1.z; part[7] += aa * w1.w;
            }
        }
#pragma unroll
        for (int o = 0; o < NOPS; o++) sOp[lb][seg][o] = part[o];
        __syncthreads();
        if (tid < 32) {
            int rb = tid >> 3, o = tid & 7;
            float s = 0.f;
            for (int g = 0; g < 64; g++) s += sOp[rb][g][o];
            sSum[rb][o] = s;
        }
        __syncthreads();
        if (tid < 4) {
            float best = __int_as_float(0xff800000); int bi = -1;
#pragma unroll
            for (int o = 0; o < NOPS; o++) {
                float v = sSum[tid][o] + bop[o];
                if (v > best) { best = v; bi = o; }
            }
            g_opflag[t][b0 + tid] = (bi == 0) ? 1 : 0;
        }
        return;
    }

    // ------- GEMM block: broadcast-A raw (8KB) + B raw (16KB) -------
    // warp w owns b-rows w*8..w*8+7 and ALL 128 s; lane l owns s = 4l..4l+3
    float (*sA)[K1_KC][64]   = (float(*)[K1_KC][64])smem;
    float (*sB)[K1_KC][K1_SB] = (float(*)[K1_KC][K1_SB])(smem + 2 * K1_KC * 64 * 4);

    const int g = bid - KA_GEMM0;
    const int ks = g >> 5, sb = g & 31;
    const int s0 = sb * K1_SB, k0 = ks * K1_KR;
    const int w8 = (tid >> 5) * 8;
    const int l  = tid & 31;
    const int fb = tid >> 2, fg = tid & 3;     // A fill: 1 float4/thread
    const int wk = tid >> 4, wg = tid & 15;    // B fill: 2 float4/thread

    ull acc[8][2];
#pragma unroll
    for (int p = 0; p < 8; p++) { acc[p][0] = 0ull; acc[p][1] = 0ull; }

    {   // B chunk-0 prefetch (independent of h_n) — hides the combine spin
        const float* wr = Wx + (size_t)(k0 + wk) * S + s0 + wg * 8;
        *(float4*)&sB[0][wk][wg * 8]     = *(const float4*)wr;
        *(float4*)&sB[0][wk][wg * 8 + 4] = *(const float4*)(wr + 4);
    }

    spin_until(&g_cnt_hn[t], KA_NCOMB);
    const float* __restrict__ hn = g_hn;

    {   // A chunk 0 (raw)
        float4 a = *(const float4*)&hn[fb * H + k0 + fg * 4];
        sA[0][fg * 4 + 0][fb] = a.x;
        sA[0][fg * 4 + 1][fb] = a.y;
        sA[0][fg * 4 + 2][fb] = a.z;
        sA[0][fg * 4 + 3][fb] = a.w;
    }
    __syncthreads();

    for (int c = 0; c < K1_NC; c++) {
        const int cur = c & 1;
        float4 pa, pw0, pw1;
        if (c + 1 < K1_NC) {
            const int kb = k0 + (c + 1) * K1_KC;
            pa = *(const float4*)&hn[fb * H + kb + fg * 4];
            const float* wr = Wx + (size_t)(kb + wk) * S + s0 + wg * 8;
            pw0 = *(const float4*)wr;
            pw1 = *(const float4*)(wr + 4);
        }
#pragma unroll
        for (int kk = 0; kk < K1_KC; kk++) {
            ulonglong2 bv = *(const ulonglong2*)&sB[cur][kk][l * 4];  // 4 raw s
            float4 a03 = *(const float4*)&sA[cur][kk][w8];            // broadcast
            float4 a47 = *(const float4*)&sA[cur][kk][w8 + 4];        // broadcast
            ull ad[8];
            ad[0] = pk2(a03.x); ad[1] = pk2(a03.y);
            ad[2] = pk2(a03.z); ad[3] = pk2(a03.w);
            ad[4] = pk2(a47.x); ad[5] = pk2(a47.y);
            ad[6] = pk2(a47.z); ad[7] = pk2(a47.w);
#pragma unroll
            for (int p = 0; p < 8; p++) {
                acc[p][0] = ffma2(ad[p], bv.x, acc[p][0]);
                acc[p][1] = ffma2(ad[p], bv.y, acc[p][1]);
            }
        }
        if (c + 1 < K1_NC) {
            const int nxt = (c + 1) & 1;
            sA[nxt][fg * 4 + 0][fb] = pa.x;
            sA[nxt][fg * 4 + 1][fb] = pa.y;
            sA[nxt][fg * 4 + 2][fb] = pa.z;
            sA[nxt][fg * 4 + 3][fb] = pa.w;
            *(float4*)&sB[nxt][wk][wg * 8]     = pw0;
            *(float4*)&sB[nxt][wk][wg * 8 + 4] = pw1;
            __syncthreads();
        }
    }

    // epilogue: lane l owns s = s0 + 4l..4l+3 for its warp's 8 b-rows
#pragma unroll
    for (int p = 0; p < 8; p++) {
        *(ulonglong2*)&g_px[ks][w8 + p][s0 + l * 4] =
            make_ulonglong2(acc[p][0], acc[p][1]);
    }
}

// ============ KB: argmax partial blocks + update GEMM (spin for gather) =====
__global__ __launch_bounds__(128) void kb(
    int t, const float* __restrict__ s2a, const float* __restrict__ Wres,
    const float* __restrict__ bx)
{
    const int tid = threadIdx.x;

    if (blockIdx.x < NAMB) {
        // ------- argmax partial block: one (b, 512-wide s segment) -------
        __shared__ ull red[4];
        const int b = blockIdx.x >> 3;
        const int s = (blockIdx.x & 7) * 512 + tid * 4;
        float4 v = *(const float4*)&bx[s];
#pragma unroll
        for (int ks = 0; ks < K1_KSPLIT; ks++) {
            float4 p = *(const float4*)&g_px[ks][b][s];
            v.x += p.x; v.y += p.y; v.z += p.z; v.w += p.w;
        }
        float best = v.x; int bi = s;
        if (v.y > best) { best = v.y; bi = s + 1; }
        if (v.z > best) { best = v.z; bi = s + 2; }
        if (v.w > best) { best = v.w; bi = s + 3; }
        ull key = ((ull)f2ord(best) << 32) | (ull)(0xFFFFFFFFu - (unsigned)bi);
#pragma unroll
        for (int off = 16; off; off >>= 1) {
            ull o = __shfl_down_sync(0xFFFFFFFFu, key, off);
            if (o > key) key = o;
        }
        if ((tid & 31) == 0) red[tid >> 5] = key;
        __syncthreads();
        if (tid == 0) {
            ull k = red[0];
#pragma unroll
            for (int w = 1; w < 4; w++) if (red[w] > k) k = red[w];
            atomicMax(&g_amax[b], k);
            __threadfence();
            atomicAdd(&g_arrived, 1);
        }
        return;
    }

    // ------- update GEMM block -------
    if (g_done_flag[t]) return;   // frozen: keep pu (h stays fixed)

    __shared__ __align__(16) float2 sA[2][K2_KC][B];
    __shared__ __align__(16) float  sB[2][K2_KC][K2_JB];
    __shared__ int sPtr[B];

    const int q = blockIdx.x - NAMB;
    const int ks = q >> 4, jb = q & 15;
    const int k0 = ks * K2_KR, j0 = jb * K2_JB;
    const bool gat = (k0 >= H);
    const float* __restrict__ hn = g_hn;
    const int jx = tid & 7, byy = tid >> 3;
    const int fbA = tid >> 1, fgA = tid & 1;
    const int wkB = tid >> 3, wgB = tid & 7;

    // prefetch B chunk 0 (Wres: independent of ptr)
    {
        const float* wr = Wres + (size_t)(k0 + wkB) * H + j0 + wgB * 8;
        *(float4*)&sB[0][wkB][wgB * 8]     = *(const float4*)wr;
        *(float4*)&sB[0][wkB][wgB * 8 + 4] = *(const float4*)(wr + 4);
    }

    if (gat) {
        spin_until(&g_arrived, NAMB);
        if (tid < B) {
            ull k = g_amax[tid];
            int p = (int)(0xFFFFFFFFu - (unsigned)(k & 0xFFFFFFFFull));
            sPtr[tid] = (p < S) ? p : (S - 1);
        }
        __syncthreads();
    }

    const float* arow = gat ? s2a + ((size_t)fbA * S + sPtr[fbA]) * H + (k0 - H)
                            : hn + fbA * H + k0;

    {   // A chunk 0
        float4 a0 = *(const float4*)(arow + fgA * 8);
        float4 a1 = *(const float4*)(arow + fgA * 8 + 4);
        sA[0][fgA * 8 + 0][fbA] = dupf(a0.x);
        sA[0][fgA * 8 + 1][fbA] = dupf(a0.y);
        sA[0][fgA * 8 + 2][fbA] = dupf(a0.z);
        sA[0][fgA * 8 + 3][fbA] = dupf(a0.w);
        sA[0][fgA * 8 + 4][fbA] = dupf(a1.x);
        sA[0][fgA * 8 + 5][fbA] = dupf(a1.y);
        sA[0][fgA * 8 + 6][fbA] = dupf(a1.z);
        sA[0][fgA * 8 + 7][fbA] = dupf(a1.w);
    }
    __syncthreads();

    ull acc[4][4];
#pragma unroll
    for (int p = 0; p < 4; p++)
#pragma unroll
        for (int q2 = 0; q2 < 4; q2++) acc[p][q2] = 0ull;

    for (int c = 0; c < K2_NC; c++) {
        const int cur = c & 1;
        float4 pa0, pa1, pw0, pw1;
        if (c + 1 < K2_NC) {
            const int kof = (c + 1) * K2_KC;
            pa0 = *(const float4*)(arow + kof + fgA * 8);
            pa1 = *(const float4*)(arow + kof + fgA * 8 + 4);
            const float* wr = Wres + (size_t)(k0 + kof + wkB) * H + j0 + wgB * 8;
            pw0 = *(const float4*)wr;
            pw1 = *(const float4*)(wr + 4);
        }
#pragma unroll
        for (int kk = 0; kk < K2_KC; kk++) {
            ulonglong2 a01 = *(const ulonglong2*)&sA[cur][kk][byy * 4];
            ulonglong2 a23 = *(const ulonglong2*)&sA[cur][kk][byy * 4 + 2];
            ulonglong2 w01 = *(const ulonglong2*)&sB[cur][kk][jx * 4];
            ulonglong2 w23 = *(const ulonglong2*)&sB[cur][kk][32 + jx * 4];
            ull av[4] = {a01.x, a01.y, a23.x, a23.y};
#pragma unroll
            for (int p = 0; p < 4; p++) {
                acc[p][0] = ffma2(av[p], w01.x, acc[p][0]);
                acc[p][1] = ffma2(av[p], w01.y, acc[p][1]);
                acc[p][2] = ffma2(av[p], w23.x, acc[p][2]);
                acc[p][3] = ffma2(av[p], w23.y, acc[p][3]);
            }
        }
        if (c + 1 < K2_NC) {
            const int nxt = (c + 1) & 1;
            sA[nxt][fgA * 8 + 0][fbA] = dupf(pa0.x);
            sA[nxt][fgA * 8 + 1][fbA] = dupf(pa0.y);
            sA[nxt][fgA * 8 + 2][fbA] = dupf(pa0.z);
            sA[nxt][fgA * 8 + 3][fbA] = dupf(pa0.w);
            sA[nxt][fgA * 8 + 4][fbA] = dupf(pa1.x);
            sA[nxt][fgA * 8 + 5][fbA] = dupf(pa1.y);
            sA[nxt][fgA * 8 + 6][fbA] = dupf(pa1.z);
            sA[nxt][fgA * 8 + 7][fbA] = dupf(pa1.w);
            *(float4*)&sB[nxt][wkB][wgB * 8]     = pw0;
            *(float4*)&sB[nxt][wkB][wgB * 8 + 4] = pw1;
            __syncthreads();
        }
    }

#pragma unroll
    for (int p = 0; p < 4; p++) {
        const int b = byy * 4 + p;
        *(ulonglong2*)&g_pu[ks][b][j0 + jx * 4]      = make_ulonglong2(acc[p][0], acc[p][1]);
        *(ulonglong2*)&g_pu[ks][b][j0 + 32 + jx * 4] = make_ulonglong2(acc[p][2], acc[p][3]);
    }
}

// ===================== KO: final combine -> out + counter resets ============
__global__ __launch_bounds__(256) void ko(const float* __restrict__ bres,
                                          float* __restrict__ out)
{
    const int b = blockIdx.x, tid = threadIdx.x;
    const int j = tid * 4;
    float4 a = make_float4(0.f, 0.f, 0.f, 0.f);
#pragma unroll
    for (int ks = 0; ks < K2_KSPLIT; ks++) {
        float4 p = *(const float4*)&g_pu[ks][b][j];
        a.x += p.x; a.y += p.y; a.z += p.z; a.w += p.w;
    }
    float4 bb = *(const float4*)&bres[j];
    *(float4*)&out[b * H + j] = make_float4(a.x + bb.x, a.y + bb.y,
                                            a.z + bb.z, a.w + bb.w);
    if (blockIdx.x == 0 && tid < TSTEPS) g_cnt_hn[tid] = 0;
}

extern "C" void kernel_launch(void* const* d_in, const int* in_sizes, int n_in,
                              void* d_out, int out_size) {
    const float* s2a   = (const float*)d_in[0];
    const float* Wres  = (const float*)d_in[1];
    const float* bres  = (const float*)d_in[2];
    const float* Wop   = (const float*)d_in[3];
    const float* bop   = (const float*)d_in[4];
    const float* Wx    = (const float*)d_in[5];
    const float* bx    = (const float*)d_in[6];
    const float* noise = (const float*)d_in[7];
    float* out = (float*)d_out;

    for (int t = 0; t < TSTEPS; t++) {
        ka<<<KA_GRID, 256>>>(t, Wx, Wop, bop, bres, noise);
        kb<<<KB_GRID, 128>>>(t, s2a, Wres, bx);
    }
    ko<<<B, 256>>>(bres, out);
}

// round 14
// speedup vs baseline: 1.4973x; 1.0660x over previous
#include <cuda_runtime.h>
#include <stdint.h>

#define B 64
#define H 1024
#define S 4096
#define NOPS 8
#define TSTEPS 10

typedef unsigned long long ull;

// ---- ka: 64 combine + 1 ctrl + 16 op + 512 GEMM (tile 64b x 128s, split 16) --
#define K1_SB 128
#define K1_NSB (S / K1_SB)           // 32
#define K1_KSPLIT 16
#define K1_KR (H / K1_KSPLIT)        // 64
#define K1_KC 16
#define K1_NC (K1_KR / K1_KC)        // 4
#define K1_GEMM (K1_NSB * K1_KSPLIT) // 512
#define KA_NCOMB 64
#define KA_CTRL  64
#define KA_OP0   65
#define KA_NOPB  16
#define KA_GEMM0 (KA_OP0 + KA_NOPB)  // 81
#define KA_GRID  (KA_GEMM0 + K1_GEMM) // 593

// ka smem: sA raw 2*16*64*4 = 8 KB, sB raw 2*16*128*4 = 16 KB
#define KA_SMEM (2 * K1_KC * 64 * 4 + 2 * K1_KC * K1_SB * 4)

// ---- kb (update): tile 64b x 64j, K-split 16, 128-thr blocks ----
#define K2_JB 64
#define K2_NJB (H / K2_JB)           // 16
#define K2_KSPLIT 16
#define K2_K (2 * H)
#define K2_KR (K2_K / K2_KSPLIT)     // 128
#define K2_KC 16
#define K2_NC (K2_KR / K2_KC)        // 8
#define K2_GEMM (K2_NJB * K2_KSPLIT) // 256
#define NAMB 512
#define KB_GRID (NAMB + K2_GEMM)     // 768

// ---- persistent scratch ----
__device__ float g_hn[B * H];
__device__ float g_px[K1_KSPLIT][B][S];   // 16 MB
__device__ float g_pu[K2_KSPLIT][B][H];   // 4 MB
__device__ ull   g_amax[B];
__device__ int   g_opflag[TSTEPS][B];
__device__ int   g_done_flag[TSTEPS];
__device__ int   g_arrived;
__device__ int   g_cnt_hn[TSTEPS];

__device__ __forceinline__ ull ffma2(ull a, ull b, ull c) {
    ull d;
    asm("fma.rn.f32x2 %0, %1, %2, %3;" : "=l"(d) : "l"(a), "l"(b), "l"(c));
    return d;
}
__device__ __forceinline__ ull pk2(float x) {   // (x,x) packed
    ull r;
    asm("mov.b64 %0, {%1, %2};" : "=l"(r) : "f"(x), "f"(x));
    return r;
}
__device__ __forceinline__ unsigned f2ord(float f) {
    unsigned u = __float_as_uint(f);
    return (u & 0x80000000u) ? ~u : (u | 0x80000000u);
}

// contention-free spin: volatile LOAD (no LTS RMW serialization); fence = acquire
__device__ __forceinline__ void spin_until(int* cnt, int target) {
    if (threadIdx.x == 0) {
        while (*(volatile int*)cnt < target) __nanosleep(64);
    }
    __syncthreads();
    __threadfence();
}

// ============ KA: combine + ctrl + op-logits + x-logit GEMM =================
__global__ __launch_bounds__(256) void ka(
    int t, const float* __restrict__ Wx,
    const float* __restrict__ Wop, const float* __restrict__ bop,
    const float* __restrict__ bres, const float* __restrict__ noise)
{
    __shared__ __align__(16) char smem[KA_SMEM];
    const int tid = threadIdx.x;
    const int bid = blockIdx.x;

    if (bid < KA_NCOMB) {
        // ------- combine block: one batch row, 256 j-quads, MLP-16 -------
        const int b = bid;
        const int j = tid * 4;
        float4 a = make_float4(0.f, 0.f, 0.f, 0.f);
        if (t > 0) {
#pragma unroll
            for (int ks = 0; ks < K2_KSPLIT; ks++) {
                float4 p = *(const float4*)&g_pu[ks][b][j];
                a.x += p.x; a.y += p.y; a.z += p.z; a.w += p.w;
            }
            float4 bb = *(const float4*)&bres[j];
            a.x += bb.x; a.y += bb.y; a.z += bb.z; a.w += bb.w;
        }
        float4 nz = *(const float4*)&noise[((size_t)t * B + b) * H + j];
        *(float4*)&g_hn[b * H + j] =
            make_float4(a.x + 0.01f * nz.x, a.y + 0.01f * nz.y,
                        a.z + 0.01f * nz.z, a.w + 0.01f * nz.w);
        __threadfence();
        __syncthreads();
        if (tid == 0) atomicAdd(&g_cnt_hn[t], 1);
        return;
    }

    if (bid == KA_CTRL) {
        // ------- ctrl: done flag + per-step resets (before kb launches) ---
        int dn = 0;
        for (int tp = 0; tp < t; tp++) {
            int f = (tid < B) ? g_opflag[tp][tid] : 1;
            dn |= __syncthreads_and(f);
        }
        if (tid == 0) { g_done_flag[t] = dn; g_arrived = 0; }
        if (tid < B) g_amax[tid] = 0ull;
        return;
    }

    if (bid < KA_GEMM0) {
        // ------- op-logits block: 4 batch rows, full K -------
        float (*sOp)[64][NOPS] = (float(*)[64][NOPS])smem;               // 8 KB
        float (*sSum)[NOPS] = (float(*)[NOPS])(smem + 4 * 64 * NOPS * 4 + 128);
        spin_until(&g_cnt_hn[t], KA_NCOMB);
        const float* __restrict__ hn = g_hn;
        const int b0 = (bid - KA_OP0) * 4;
        const int lb = tid >> 6, seg = tid & 63;
        const int b = b0 + lb, kb = seg * 16;
        float part[NOPS];
#pragma unroll
        for (int o = 0; o < NOPS; o++) part[o] = 0.f;
        const float4* wp = (const float4*)(Wop + (size_t)kb * NOPS);
#pragma unroll
        for (int g = 0; g < 4; g++) {
            float4 a4 = *(const float4*)&hn[b * H + kb + g * 4];
            float av[4] = {a4.x, a4.y, a4.z, a4.w};
#pragma unroll
            for (int c = 0; c < 4; c++) {
                float4 w0 = wp[(g * 4 + c) * 2], w1 = wp[(g * 4 + c) * 2 + 1];
                float aa = av[c];
                part[0] += aa * w0.x; part[1] += aa * w0.y;
                part[2] += aa * w0.z; part[3] += aa * w0.w;
                part[4] += aa * w1.x; part[5] += aa * w1.y;
                part[6] += aa * w1.z; part[7] += aa * w1.w;
            }
        }
#pragma unroll
        for (int o = 0; o < NOPS; o++) sOp[lb][seg][o] = part[o];
        __syncthreads();
        if (tid < 32) {
            int rb = tid >> 3, o = tid & 7;
            float s = 0.f;
            for (int g = 0; g < 64; g++) s += sOp[rb][g][o];
            sSum[rb][o] = s;
        }
        __syncthreads();
        if (tid < 4) {
            float best = __int_as_float(0xff800000); int bi = -1;
#pragma unroll
            for (int o = 0; o < NOPS; o++) {
                float v = sSum[tid][o] + bop[o];
                if (v > best) { best = v; bi = o; }
            }
            g_opflag[t][b0 + tid] = (bi == 0) ? 1 : 0;
        }
        return;
    }

    // ------- GEMM block: broadcast-A raw (8KB) + B raw (16KB) -------
    float (*sA)[K1_KC][64]   = (float(*)[K1_KC][64])smem;
    float (*sB)[K1_KC][K1_SB] = (float(*)[K1_KC][K1_SB])(smem + 2 * K1_KC * 64 * 4);

    const int g = bid - KA_GEMM0;
    const int ks = g >> 5, sb = g & 31;
    const int s0 = sb * K1_SB, k0 = ks * K1_KR;
    const int w8 = (tid >> 5) * 8;
    const int l  = tid & 31;
    const int fb = tid >> 2, fg = tid & 3;     // A fill: 1 float4/thread
    const int wk = tid >> 4, wg = tid & 15;    // B fill: 2 float4/thread

    ull acc[8][2];
#pragma unroll
    for (int p = 0; p < 8; p++) { acc[p][0] = 0ull; acc[p][1] = 0ull; }

    {   // B chunk-0 prefetch (independent of h_n) — hides the combine spin
        const float* wr = Wx + (size_t)(k0 + wk) * S + s0 + wg * 8;
        *(float4*)&sB[0][wk][wg * 8]     = *(const float4*)wr;
        *(float4*)&sB[0][wk][wg * 8 + 4] = *(const float4*)(wr + 4);
    }

    spin_until(&g_cnt_hn[t], KA_NCOMB);
    const float* __restrict__ hn = g_hn;

    {   // A chunk 0 (raw)
        float4 a = *(const float4*)&hn[fb * H + k0 + fg * 4];
        sA[0][fg * 4 + 0][fb] = a.x;
        sA[0][fg * 4 + 1][fb] = a.y;
        sA[0][fg * 4 + 2][fb] = a.z;
        sA[0][fg * 4 + 3][fb] = a.w;
    }
    __syncthreads();

    for (int c = 0; c < K1_NC; c++) {
        const int cur = c & 1;
        float4 pa, pw0, pw1;
        if (c + 1 < K1_NC) {
            const int kb = k0 + (c + 1) * K1_KC;
            pa = *(const float4*)&hn[fb * H + kb + fg * 4];
            const float* wr = Wx + (size_t)(kb + wk) * S + s0 + wg * 8;
            pw0 = *(const float4*)wr;
            pw1 = *(const float4*)(wr + 4);
        }
#pragma unroll
        for (int kk = 0; kk < K1_KC; kk++) {
            ulonglong2 bv = *(const ulonglong2*)&sB[cur][kk][l * 4];  // 4 raw s
            float4 a03 = *(const float4*)&sA[cur][kk][w8];            // broadcast
            float4 a47 = *(const float4*)&sA[cur][kk][w8 + 4];        // broadcast
            ull ad[8];
            ad[0] = pk2(a03.x); ad[1] = pk2(a03.y);
            ad[2] = pk2(a03.z); ad[3] = pk2(a03.w);
            ad[4] = pk2(a47.x); ad[5] = pk2(a47.y);
            ad[6] = pk2(a47.z); ad[7] = pk2(a47.w);
#pragma unroll
            for (int p = 0; p < 8; p++) {
                acc[p][0] = ffma2(ad[p], bv.x, acc[p][0]);
                acc[p][1] = ffma2(ad[p], bv.y, acc[p][1]);
            }
        }
        if (c + 1 < K1_NC) {
            const int nxt = (c + 1) & 1;
            sA[nxt][fg * 4 + 0][fb] = pa.x;
            sA[nxt][fg * 4 + 1][fb] = pa.y;
            sA[nxt][fg * 4 + 2][fb] = pa.z;
            sA[nxt][fg * 4 + 3][fb] = pa.w;
            *(float4*)&sB[nxt][wk][wg * 8]     = pw0;
            *(float4*)&sB[nxt][wk][wg * 8 + 4] = pw1;
            __syncthreads();
        }
    }

    // epilogue: lane l owns s = s0 + 4l..4l+3 for its warp's 8 b-rows
#pragma unroll
    for (int p = 0; p < 8; p++) {
        *(ulonglong2*)&g_px[ks][w8 + p][s0 + l * 4] =
            make_ulonglong2(acc[p][0], acc[p][1]);
    }
}

// ============ KB: argmax partial blocks + update GEMM (spin for gather) =====
__global__ __launch_bounds__(128) void kb(
    int t, const float* __restrict__ s2a, const float* __restrict__ Wres,
    const float* __restrict__ bx)
{
    __shared__ __align__(16) char smem[2 * K2_KC * 64 * 4 + 2 * K2_KC * K2_JB * 4 + 512];
    const int tid = threadIdx.x;

    if (blockIdx.x < NAMB) {
        // ------- argmax partial block: one (b, 512-wide s segment) -------
        ull* red = (ull*)smem;
        const int b = blockIdx.x >> 3;
        const int s = (blockIdx.x & 7) * 512 + tid * 4;
        float4 v = *(const float4*)&bx[s];
#pragma unroll
        for (int ks = 0; ks < K1_KSPLIT; ks++) {
            float4 p = *(const float4*)&g_px[ks][b][s];
            v.x += p.x; v.y += p.y; v.z += p.z; v.w += p.w;
        }
        float best = v.x; int bi = s;
        if (v.y > best) { best = v.y; bi = s + 1; }
        if (v.z > best) { best = v.z; bi = s + 2; }
        if (v.w > best) { best = v.w; bi = s + 3; }
        ull key = ((ull)f2ord(best) << 32) | (ull)(0xFFFFFFFFu - (unsigned)bi);
#pragma unroll
        for (int off = 16; off; off >>= 1) {
            ull o = __shfl_down_sync(0xFFFFFFFFu, key, off);
            if (o > key) key = o;
        }
        if ((tid & 31) == 0) red[tid >> 5] = key;
        __syncthreads();
        if (tid == 0) {
            ull k = red[0];
#pragma unroll
            for (int w = 1; w < 4; w++) if (red[w] > k) k = red[w];
            atomicMax(&g_amax[b], k);
            __threadfence();
            atomicAdd(&g_arrived, 1);
        }
        return;
    }

    // ------- update GEMM block: broadcast-A raw (8KB) + B raw (8KB) -------
    // thread = (byy 0..7 owning 8 b-rows, jx 0..15 owning 4 j)
    if (g_done_flag[t]) return;   // frozen: keep pu (h stays fixed)

    float (*sA)[K2_KC][64] = (float(*)[K2_KC][64])smem;
    float (*sB)[K2_KC][K2_JB] = (float(*)[K2_KC][K2_JB])(smem + 2 * K2_KC * 64 * 4);
    int* sPtr = (int*)(smem + 2 * K2_KC * 64 * 4 + 2 * K2_KC * K2_JB * 4);

    const int q = blockIdx.x - NAMB;
    const int ks = q >> 4, jb = q & 15;
    const int k0 = ks * K2_KR, j0 = jb * K2_JB;
    const bool gat = (k0 >= H);
    const float* __restrict__ hn = g_hn;
    const int jx = tid & 15, byy = tid >> 4;
    const int fbA = tid >> 1, fgA = tid & 1;   // A fill: 2 float4/thread
    const int wkB = tid >> 3, wgB = tid & 7;   // B fill: 2 float4/thread

    // prefetch B chunk 0 (Wres: independent of ptr)
    {
        const float* wr = Wres + (size_t)(k0 + wkB) * H + j0 + wgB * 8;
        *(float4*)&sB[0][wkB][wgB * 8]     = *(const float4*)wr;
        *(float4*)&sB[0][wkB][wgB * 8 + 4] = *(const float4*)(wr + 4);
    }

    if (gat) {
        spin_until(&g_arrived, NAMB);
        if (tid < B) {
            ull k = g_amax[tid];
            int p = (int)(0xFFFFFFFFu - (unsigned)(k & 0xFFFFFFFFull));
            sPtr[tid] = (p < S) ? p : (S - 1);
        }
        __syncthreads();
    }

    const float* arow = gat ? s2a + ((size_t)fbA * S + sPtr[fbA]) * H + (k0 - H)
                            : hn + fbA * H + k0;

    {   // A chunk 0 (raw)
        float4 a0 = *(const float4*)(arow + fgA * 8);
        float4 a1 = *(const float4*)(arow + fgA * 8 + 4);
        sA[0][fgA * 8 + 0][fbA] = a0.x;
        sA[0][fgA * 8 + 1][fbA] = a0.y;
        sA[0][fgA * 8 + 2][fbA] = a0.z;
        sA[0][fgA * 8 + 3][fbA] = a0.w;
        sA[0][fgA * 8 + 4][fbA] = a1.x;
        sA[0][fgA * 8 + 5][fbA] = a1.y;
        sA[0][fgA * 8 + 6][fbA] = a1.z;
        sA[0][fgA * 8 + 7][fbA] = a1.w;
    }
    __syncthreads();

    ull acc[8][2];
#pragma unroll
    for (int p = 0; p < 8; p++) { acc[p][0] = 0ull; acc[p][1] = 0ull; }

    for (int c = 0; c < K2_NC; c++) {
        const int cur = c & 1;
        float4 pa0, pa1, pw0, pw1;
        if (c + 1 < K2_NC) {
            const int kof = (c + 1) * K2_KC;
            pa0 = *(const float4*)(arow + kof + fgA * 8);
            pa1 = *(const float4*)(arow + kof + fgA * 8 + 4);
            const float* wr = Wres + (size_t)(k0 + kof + wkB) * H + j0 + wgB * 8;
            pw0 = *(const float4*)wr;
            pw1 = *(const float4*)(wr + 4);
        }
#pragma unroll
        for (int kk = 0; kk < K2_KC; kk++) {
            ulonglong2 bv = *(const ulonglong2*)&sB[cur][kk][jx * 4];  // 4 raw j
            float4 a03 = *(const float4*)&sA[cur][kk][byy * 8];        // broadcast
            float4 a47 = *(const float4*)&sA[cur][kk][byy * 8 + 4];    // broadcast
            ull ad[8];
            ad[0] = pk2(a03.x); ad[1] = pk2(a03.y);
            ad[2] = pk2(a03.z); ad[3] = pk2(a03.w);
            ad[4] = pk2(a47.x); ad[5] = pk2(a47.y);
            ad[6] = pk2(a47.z); ad[7] = pk2(a47.w);
#pragma unroll
            for (int p = 0; p < 8; p++) {
                acc[p][0] = ffma2(ad[p], bv.x, acc[p][0]);
                acc[p][1] = ffma2(ad[p], bv.y, acc[p][1]);
            }
        }
        if (c + 1 < K2_NC) {
            const int nxt = (c + 1) & 1;
            sA[nxt][fgA * 8 + 0][fbA] = pa0.x;
            sA[nxt][fgA * 8 + 1][fbA] = pa0.y;
            sA[nxt][fgA * 8 + 2][fbA] = pa0.z;
            sA[nxt][fgA * 8 + 3][fbA] = pa0.w;
            sA[nxt][fgA * 8 + 4][fbA] = pa1.x;
            sA[nxt][fgA * 8 + 5][fbA] = pa1.y;
            sA[nxt][fgA * 8 + 6][fbA] = pa1.z;
            sA[nxt][fgA * 8 + 7][fbA] = pa1.w;
            *(float4*)&sB[nxt][wkB][wgB * 8]     = pw0;
            *(float4*)&sB[nxt][wkB][wgB * 8 + 4] = pw1;
            __syncthreads();
        }
    }

    // epilogue: thread (byy, jx) owns b-rows byy*8..+7, j = j0 + jx*4
#pragma unroll
    for (int p = 0; p < 8; p++) {
        *(ulonglong2*)&g_pu[ks][byy * 8 + p][j0 + jx * 4] =
            make_ulonglong2(acc[p][0], acc[p][1]);
    }
}

// ===================== KO: final combine -> out + counter resets ============
__global__ __launch_bounds__(256) void ko(const float* __restrict__ bres,
                                          float* __restrict__ out)
{
    const int b = blockIdx.x, tid = threadIdx.x;
    const int j = tid * 4;
    float4 a = make_float4(0.f, 0.f, 0.f, 0.f);
#pragma unroll
    for (int ks = 0; ks < K2_KSPLIT; ks++) {
        float4 p = *(const float4*)&g_pu[ks][b][j];
        a.x += p.x; a.y += p.y; a.z += p.z; a.w += p.w;
    }
    float4 bb = *(const float4*)&bres[j];
    *(float4*)&out[b * H + j] = make_float4(a.x + bb.x, a.y + bb.y,
                                            a.z + bb.z, a.w + bb.w);
    if (blockIdx.x == 0 && tid < TSTEPS) g_cnt_hn[tid] = 0;
}

extern "C" void kernel_launch(void* const* d_in, const int* in_sizes, int n_in,
                              void* d_out, int out_size) {
    const float* s2a   = (const float*)d_in[0];
    const float* Wres  = (const float*)d_in[1];
    const float* bres  = (const float*)d_in[2];
    const float* Wop   = (const float*)d_in[3];
    const float* bop   = (const float*)d_in[4];
    const float* Wx    = (const float*)d_in[5];
    const float* bx    = (const float*)d_in[6];
    const float* noise = (const float*)d_in[7];
    float* out = (float*)d_out;

    for (int t = 0; t < TSTEPS; t++) {
        ka<<<KA_GRID, 256>>>(t, Wx, Wop, bop, bres, noise);
        kb<<<KB_GRID, 128>>>(t, s2a, Wres, bx);
    }
    ko<<<B, 256>>>(bres, out);
}